// round 11
// baseline (speedup 1.0000x reference)
#include <cuda_runtime.h>

#define BB   8
#define NN   6
#define MM   64
#define VV   32000
#define TT   8
#define NP1  7
#define CHUNKS (VV / 4)   // 8000 float4 per row
#define THR  256
#define NWARP (THR / 32)

__device__ unsigned char g_flags[BB * TT * MM];  // argmax==0 flag per (b,t,m)
__device__ int           g_needed[BB];           // does b need t>=1 flags?
__device__ int           g_src[BB * MM];         // t*64 + m_src, or -1

// ---------------------------------------------------------------------------
// Pass 1 (t = 0 ONLY): compute the t=0 projection per (b,m) row, store it
// speculatively to d_out, and emit flag[t=0] = (out[v=0] >= max_v out[v]).
// 6 FMA / element -> decisively memory-bound (393 MB R + 65 MB W).
// ---------------------------------------------------------------------------
__global__ __launch_bounds__(THR) void t0_kernel(
    const float* __restrict__ x,      // [B,N,M,V]
    const float* __restrict__ tmpl,   // [B,T,N+1]
    const int*   __restrict__ spans,  // [B]
    float*       __restrict__ out)    // [B,M,V]
{
    const int bm = blockIdx.x;
    const int b = bm >> 6;
    const int m = bm & 63;
    const int tid = threadIdx.x;

    __shared__ float sw[NN];
    __shared__ float swpad;
    __shared__ float smax[NWARP];
    __shared__ float sout0;

    if (tid < NN)
        sw[tid] = ((tid + 1) <= spans[b]) ? tmpl[(b * TT + 0) * NP1 + tid + 1] : 0.0f;
    if (tid == NN)
        swpad = tmpl[(b * TT + 0) * NP1];   // pad weight (s=0 always unmasked)
    __syncthreads();

    float wl[NN];
#pragma unroll
    for (int n = 0; n < NN; n++) wl[n] = sw[n];

    const float4* xr[NN];
#pragma unroll
    for (int n = 0; n < NN; n++)
        xr[n] = (const float4*)(x + (size_t)((b * NN + n) * MM + m) * VV);
    float4* orow = (float4*)(out + (size_t)(b * MM + m) * VV);

    float vmax = -3.402823466e38f;

    for (int c = tid; c < CHUNKS; c += THR) {
        float4 xs[NN];
#pragma unroll
        for (int n = 0; n < NN; n++) xs[n] = xr[n][c];
        float ax = wl[0] * xs[0].x;
        float ay = wl[0] * xs[0].y;
        float az = wl[0] * xs[0].z;
        float aw = wl[0] * xs[0].w;
#pragma unroll
        for (int n = 1; n < NN; n++) {
            ax = fmaf(wl[n], xs[n].x, ax);
            ay = fmaf(wl[n], xs[n].y, ay);
            az = fmaf(wl[n], xs[n].z, az);
            aw = fmaf(wl[n], xs[n].w, aw);
        }
        if (c == 0) {                    // only tid==0 hits c==0
            if (m == 0) ax += swpad;     // pad one-hot lands at (m=0, v=0)
            sout0 = ax;
        }
        orow[c] = make_float4(ax, ay, az, aw);   // speculative t=0 store
        vmax = fmaxf(vmax, fmaxf(fmaxf(ax, ay), fmaxf(az, aw)));
    }

    // reduce max over the block
#pragma unroll
    for (int o = 16; o > 0; o >>= 1)
        vmax = fmaxf(vmax, __shfl_xor_sync(0xffffffffu, vmax, o));
    if ((tid & 31) == 0) smax[tid >> 5] = vmax;
    __syncthreads();
    if (tid == 0) {
        float v = smax[0];
#pragma unroll
        for (int wd = 1; wd < NWARP; wd++) v = fmaxf(v, smax[wd]);
        g_flags[(b * TT + 0) * MM + m] = (sout0 >= v) ? 1 : 0;  // argmax==0
    }
}

// ---------------------------------------------------------------------------
// Pass 2a: per-b, does the t=0 run stop early? If len0 == 64, flags for
// t>=1 are irrelevant (scan cursor saturates at 64).
// ---------------------------------------------------------------------------
__global__ void needed_kernel()
{
    const int b = threadIdx.x;
    if (b < BB) {
        int len0 = MM;
        for (int mm = 0; mm < MM; mm++)
            if (g_flags[(b * TT + 0) * MM + mm]) { len0 = mm; break; }
        g_needed[b] = (len0 < MM) ? 1 : 0;
    }
}

// ---------------------------------------------------------------------------
// Pass 2b: flags for t = 1..7, only for batches that need them.
// Non-needed blocks exit after a single broadcast load.
// ---------------------------------------------------------------------------
__global__ __launch_bounds__(THR) void rest_flags_kernel(
    const float* __restrict__ x,
    const float* __restrict__ tmpl,
    const int*   __restrict__ spans)
{
    const int bm = blockIdx.x;
    const int b = bm >> 6;
    const int m = bm & 63;
    const int tid = threadIdx.x;

    if (!g_needed[b]) return;

    __shared__ float sw[TT][NN];     // index t = 1..7 used
    __shared__ float swpad[TT];
    __shared__ float smax[NWARP][TT];
    __shared__ float sout0[TT];

    if (tid < TT * NN) {
        const int t = tid / NN, n = tid % NN;
        if (t >= 1) {
            const int sp = spans[b];
            sw[t][n] = ((n + 1) <= sp) ? tmpl[(b * TT + t) * NP1 + n + 1] : 0.0f;
        }
    } else if (tid < TT * NN + TT) {
        const int t = tid - TT * NN;
        swpad[t] = tmpl[(b * TT + t) * NP1];
    }
    __syncthreads();

    float wl[TT][NN];
#pragma unroll
    for (int t = 1; t < TT; t++)
#pragma unroll
        for (int n = 0; n < NN; n++) wl[t][n] = sw[t][n];

    const float4* xr[NN];
#pragma unroll
    for (int n = 0; n < NN; n++)
        xr[n] = (const float4*)(x + (size_t)((b * NN + n) * MM + m) * VV);

    float vmax[TT];
#pragma unroll
    for (int t = 1; t < TT; t++) vmax[t] = -3.402823466e38f;

    for (int c = tid; c < CHUNKS; c += THR) {
        float4 xs[NN];
#pragma unroll
        for (int n = 0; n < NN; n++) xs[n] = xr[n][c];
#pragma unroll
        for (int t = 1; t < TT; t++) {
            float ax = wl[t][0] * xs[0].x;
            float ay = wl[t][0] * xs[0].y;
            float az = wl[t][0] * xs[0].z;
            float aw = wl[t][0] * xs[0].w;
#pragma unroll
            for (int n = 1; n < NN; n++) {
                ax = fmaf(wl[t][n], xs[n].x, ax);
                ay = fmaf(wl[t][n], xs[n].y, ay);
                az = fmaf(wl[t][n], xs[n].z, az);
                aw = fmaf(wl[t][n], xs[n].w, aw);
            }
            if (c == 0) {
                if (m == 0) ax += swpad[t];
                sout0[t] = ax;
            }
            vmax[t] = fmaxf(vmax[t], fmaxf(fmaxf(ax, ay), fmaxf(az, aw)));
        }
    }

#pragma unroll
    for (int t = 1; t < TT; t++) {
        float v = vmax[t];
#pragma unroll
        for (int o = 16; o > 0; o >>= 1)
            v = fmaxf(v, __shfl_xor_sync(0xffffffffu, v, o));
        if ((tid & 31) == 0) smax[tid >> 5][t] = v;
    }
    __syncthreads();
    if (tid >= 1 && tid < TT) {
        float v = smax[0][tid];
#pragma unroll
        for (int wd = 1; wd < NWARP; wd++) v = fmaxf(v, smax[wd][tid]);
        g_flags[(b * TT + tid) * MM + m] = (sout0[tid] >= v) ? 1 : 0;
    }
}

// ---------------------------------------------------------------------------
// Pass 2c: replay the sequential scan. For len0==64 batches, t>=1 lengths
// clamp to 0, so stale flags there are never consumed.
// ---------------------------------------------------------------------------
__global__ void scan_kernel()
{
    const int tid = threadIdx.x;
    for (int i = tid; i < BB * MM; i += blockDim.x) g_src[i] = -1;
    __syncthreads();
    if (tid < BB) {
        const int b = tid;
        int idx = 0;
        for (int t = 0; t < TT; t++) {
            int len = MM;
            for (int mm = 0; mm < MM; mm++) {
                if (g_flags[(b * TT + t) * MM + mm]) { len = mm; break; }
            }
            if (len > MM - idx) len = MM - idx;
            for (int j = 0; j < len; j++)
                g_src[b * MM + idx + j] = t * MM + j;
            idx += len;
        }
    }
}

// ---------------------------------------------------------------------------
// Pass 3: fix-up. src==m (speculation right) -> exit; src<0 -> zero-fill;
// else recompute the correct (t, m_src) projection.
// ---------------------------------------------------------------------------
__global__ __launch_bounds__(THR) void gather_kernel(
    const float* __restrict__ x,
    const float* __restrict__ tmpl,
    const int*   __restrict__ spans,
    float*       __restrict__ out)
{
    const int bm = blockIdx.x;
    const int b = bm >> 6;
    const int m = bm & 63;
    const int tid = threadIdx.x;

    const int src = g_src[b * MM + m];
    if (src == m) return;            // t=0 identity speculation was correct

    float4* orow = (float4*)(out + (size_t)(b * MM + m) * VV);

    if (src < 0) {
        const float4 z = make_float4(0.f, 0.f, 0.f, 0.f);
        for (int c = tid; c < CHUNKS; c += THR) orow[c] = z;
        return;
    }

    const int t  = src >> 6;
    const int ms = src & 63;

    __shared__ float sw[NN];
    __shared__ float swpad;
    if (tid < NN)
        sw[tid] = ((tid + 1) <= spans[b]) ? tmpl[(b * TT + t) * NP1 + tid + 1] : 0.0f;
    if (tid == NN)
        swpad = tmpl[(b * TT + t) * NP1];
    __syncthreads();

    float wl[NN];
#pragma unroll
    for (int n = 0; n < NN; n++) wl[n] = sw[n];

    const float4* xr[NN];
#pragma unroll
    for (int n = 0; n < NN; n++)
        xr[n] = (const float4*)(x + (size_t)((b * NN + n) * MM + ms) * VV);

    for (int c = tid; c < CHUNKS; c += THR) {
        float4 xs[NN];
#pragma unroll
        for (int n = 0; n < NN; n++) xs[n] = xr[n][c];
        float ax = wl[0] * xs[0].x;
        float ay = wl[0] * xs[0].y;
        float az = wl[0] * xs[0].z;
        float aw = wl[0] * xs[0].w;
#pragma unroll
        for (int n = 1; n < NN; n++) {
            ax = fmaf(wl[n], xs[n].x, ax);
            ay = fmaf(wl[n], xs[n].y, ay);
            az = fmaf(wl[n], xs[n].z, az);
            aw = fmaf(wl[n], xs[n].w, aw);
        }
        if (c == 0 && ms == 0) ax += swpad;
        orow[c] = make_float4(ax, ay, az, aw);
    }
}

// ---------------------------------------------------------------------------
extern "C" void kernel_launch(void* const* d_in, const int* in_sizes, int n_in,
                              void* d_out, int out_size)
{
    const float* x     = (const float*)d_in[0];   // [8,6,64,32000] f32
    const float* tmpl  = (const float*)d_in[1];   // [8,8,7] f32
    const int*   spans = (const int*)d_in[2];     // [8] int32
    float*       out   = (float*)d_out;           // [8,64,32000] f32

    t0_kernel<<<BB * MM, THR>>>(x, tmpl, spans, out);
    needed_kernel<<<1, 32>>>();
    rest_flags_kernel<<<BB * MM, THR>>>(x, tmpl, spans);
    scan_kernel<<<1, 256>>>();
    gather_kernel<<<BB * MM, THR>>>(x, tmpl, spans, out);
}

// round 15
// speedup vs baseline: 1.1168x; 1.1168x over previous
#include <cuda_runtime.h>

#define BB   8
#define NN   6
#define MM   64
#define VV   32000
#define TT   8
#define NP1  7
#define CHUNKS (VV / 4)     // 8000 float4 per row
#define HC   (CHUNKS / 2)   // 4000 float4 per half-row
#define THR  256
#define NWARP (THR / 32)

// Scratch (__device__ globals; no allocations allowed)
__device__ float         g_pmax[BB * MM * 2];    // per-(b,m,half) max of t=0 projection
__device__ float         g_out0[BB * MM];        // t=0 projection value at v=0 (incl. pad)
__device__ unsigned char g_flags[BB * TT * MM];  // argmax==0 flags for t>=1
__device__ int           g_src[BB * MM];         // t*64 + m_src, or -1

// ---------------------------------------------------------------------------
// Pass 1: t=0 projection, split over V-halves (1024 blocks for balance).
// Speculatively stores its half-row to d_out; emits partial max + out0.
// ---------------------------------------------------------------------------
__global__ __launch_bounds__(THR) void t0_kernel(
    const float* __restrict__ x,      // [B,N,M,V]
    const float* __restrict__ tmpl,   // [B,T,N+1]
    const int*   __restrict__ spans,  // [B]
    float*       __restrict__ out)    // [B,M,V]
{
    const int bm   = blockIdx.x >> 1;
    const int half = blockIdx.x & 1;
    const int b = bm >> 6;
    const int m = bm & 63;
    const int tid = threadIdx.x;

    __shared__ float sw[NN];
    __shared__ float swpad;
    __shared__ float smax[NWARP];

    if (tid < NN)
        sw[tid] = ((tid + 1) <= spans[b]) ? tmpl[(b * TT + 0) * NP1 + tid + 1] : 0.0f;
    if (tid == NN)
        swpad = tmpl[(b * TT + 0) * NP1];   // pad weight (s=0 always unmasked)
    __syncthreads();

    float wl[NN];
#pragma unroll
    for (int n = 0; n < NN; n++) wl[n] = sw[n];

    const float4* xr[NN];
#pragma unroll
    for (int n = 0; n < NN; n++)
        xr[n] = (const float4*)(x + (size_t)((b * NN + n) * MM + m) * VV);
    float4* orow = (float4*)(out + (size_t)(b * MM + m) * VV);

    float vmax = -3.402823466e38f;
    const int cbeg = half * HC, cend = cbeg + HC;

    for (int c = cbeg + tid; c < cend; c += THR) {
        float4 xs[NN];
#pragma unroll
        for (int n = 0; n < NN; n++) xs[n] = xr[n][c];
        float ax = wl[0] * xs[0].x;
        float ay = wl[0] * xs[0].y;
        float az = wl[0] * xs[0].z;
        float aw = wl[0] * xs[0].w;
#pragma unroll
        for (int n = 1; n < NN; n++) {
            ax = fmaf(wl[n], xs[n].x, ax);
            ay = fmaf(wl[n], xs[n].y, ay);
            az = fmaf(wl[n], xs[n].z, az);
            aw = fmaf(wl[n], xs[n].w, aw);
        }
        if (c == 0) {                    // only half 0, tid 0
            if (m == 0) ax += swpad;     // pad one-hot lands at (m=0, v=0)
            g_out0[bm] = ax;
        }
        orow[c] = make_float4(ax, ay, az, aw);   // speculative t=0 store
        vmax = fmaxf(vmax, fmaxf(fmaxf(ax, ay), fmaxf(az, aw)));
    }

#pragma unroll
    for (int o = 16; o > 0; o >>= 1)
        vmax = fmaxf(vmax, __shfl_xor_sync(0xffffffffu, vmax, o));
    if ((tid & 31) == 0) smax[tid >> 5] = vmax;
    __syncthreads();
    if (tid == 0) {
        float v = smax[0];
#pragma unroll
        for (int wd = 1; wd < NWARP; wd++) v = fmaxf(v, smax[wd]);
        g_pmax[bm * 2 + half] = v;
    }
}

// Helper: t=0 argmax==0 flag for row index i (= b*64+m), from partials.
__device__ __forceinline__ bool t0_flag(int i) {
    return g_out0[i] >= fmaxf(g_pmax[i * 2], g_pmax[i * 2 + 1]);
}

// ---------------------------------------------------------------------------
// Pass 2: flags for t=1..7 — self-gated. Warp 0 ballots the 64 t=0 flags of
// this batch; if none set, the t=0 run is 64 long and t>=1 never executes.
// ---------------------------------------------------------------------------
__global__ __launch_bounds__(THR) void rest_flags_kernel(
    const float* __restrict__ x,
    const float* __restrict__ tmpl,
    const int*   __restrict__ spans)
{
    const int bm = blockIdx.x;
    const int b = bm >> 6;
    const int m = bm & 63;
    const int tid = threadIdx.x;
    const int lane = tid & 31;

    __shared__ int s_need;
    if (tid < 32) {
        unsigned lo = __ballot_sync(0xffffffffu, t0_flag(b * MM + lane));
        unsigned hi = __ballot_sync(0xffffffffu, t0_flag(b * MM + 32 + lane));
        if (lane == 0) s_need = (lo | hi) != 0u;
    }
    __syncthreads();
    if (!s_need) return;

    __shared__ float sw[TT][NN];     // t = 1..7 used
    __shared__ float swpad[TT];
    __shared__ float smax[NWARP][TT];
    __shared__ float sout0[TT];

    if (tid < TT * NN) {
        const int t = tid / NN, n = tid % NN;
        if (t >= 1) {
            const int sp = spans[b];
            sw[t][n] = ((n + 1) <= sp) ? tmpl[(b * TT + t) * NP1 + n + 1] : 0.0f;
        }
    } else if (tid < TT * NN + TT) {
        const int t = tid - TT * NN;
        swpad[t] = tmpl[(b * TT + t) * NP1];
    }
    __syncthreads();

    float wl[TT][NN];
#pragma unroll
    for (int t = 1; t < TT; t++)
#pragma unroll
        for (int n = 0; n < NN; n++) wl[t][n] = sw[t][n];

    const float4* xr[NN];
#pragma unroll
    for (int n = 0; n < NN; n++)
        xr[n] = (const float4*)(x + (size_t)((b * NN + n) * MM + m) * VV);

    float vmax[TT];
#pragma unroll
    for (int t = 1; t < TT; t++) vmax[t] = -3.402823466e38f;

    for (int c = tid; c < CHUNKS; c += THR) {
        float4 xs[NN];
#pragma unroll
        for (int n = 0; n < NN; n++) xs[n] = xr[n][c];
#pragma unroll
        for (int t = 1; t < TT; t++) {
            float ax = wl[t][0] * xs[0].x;
            float ay = wl[t][0] * xs[0].y;
            float az = wl[t][0] * xs[0].z;
            float aw = wl[t][0] * xs[0].w;
#pragma unroll
            for (int n = 1; n < NN; n++) {
                ax = fmaf(wl[t][n], xs[n].x, ax);
                ay = fmaf(wl[t][n], xs[n].y, ay);
                az = fmaf(wl[t][n], xs[n].z, az);
                aw = fmaf(wl[t][n], xs[n].w, aw);
            }
            if (c == 0) {
                if (m == 0) ax += swpad[t];
                sout0[t] = ax;
            }
            vmax[t] = fmaxf(vmax[t], fmaxf(fmaxf(ax, ay), fmaxf(az, aw)));
        }
    }

#pragma unroll
    for (int t = 1; t < TT; t++) {
        float v = vmax[t];
#pragma unroll
        for (int o = 16; o > 0; o >>= 1)
            v = fmaxf(v, __shfl_xor_sync(0xffffffffu, v, o));
        if ((tid & 31) == 0) smax[tid >> 5][t] = v;
    }
    __syncthreads();
    if (tid >= 1 && tid < TT) {
        float v = smax[0][tid];
#pragma unroll
        for (int wd = 1; wd < NWARP; wd++) v = fmaxf(v, smax[wd][tid]);
        g_flags[(b * TT + tid) * MM + m] = (sout0[tid] >= v) ? 1 : 0;
    }
}

// ---------------------------------------------------------------------------
// Pass 3: ballot-based scan (replaces serial-load scan: 22.7us -> ~3us).
// Builds 64-bit masks per (b,t) via ballots, lengths via ffsll, cursor scan
// in smem, coalesced g_src writeout. Stale t>=1 flags for len0==64 batches
// are never consumed (cursor saturates at 64).
// ---------------------------------------------------------------------------
__global__ __launch_bounds__(THR) void scan_kernel()
{
    __shared__ unsigned long long mask[BB][TT];
    __shared__ int slen[BB][TT];
    __shared__ int ssrc[BB * MM];

    const int tid = threadIdx.x;
    const int warp = tid >> 5, lane = tid & 31;

    for (int i = tid; i < BB * MM; i += THR) ssrc[i] = -1;

    // t=0 masks from partials: warp w handles batch w
    {
        const int b = warp;
        unsigned lo = __ballot_sync(0xffffffffu, t0_flag(b * MM + lane));
        unsigned hi = __ballot_sync(0xffffffffu, t0_flag(b * MM + 32 + lane));
        if (lane == 0)
            mask[b][0] = (unsigned long long)lo | ((unsigned long long)hi << 32);
    }
    // t=1..7 masks from g_flags: 56 rows over 8 warps, 7 rounds
    for (int rr = warp; rr < BB * (TT - 1); rr += NWARP) {
        const int b = rr / (TT - 1);
        const int t = 1 + rr % (TT - 1);
        const unsigned char* fr = &g_flags[(b * TT + t) * MM];
        unsigned lo = __ballot_sync(0xffffffffu, fr[lane] != 0);
        unsigned hi = __ballot_sync(0xffffffffu, fr[32 + lane] != 0);
        if (lane == 0)
            mask[b][t] = (unsigned long long)lo | ((unsigned long long)hi << 32);
    }
    __syncthreads();

    if (tid < BB * TT) {
        unsigned long long mk = mask[tid >> 3][tid & 7];
        slen[tid >> 3][tid & 7] = mk ? (__ffsll((long long)mk) - 1) : MM;
    }
    __syncthreads();

    if (tid < BB) {
        const int b = tid;
        int idx = 0;
#pragma unroll
        for (int t = 0; t < TT; t++) {
            int len = slen[b][t];
            if (len > MM - idx) len = MM - idx;
            for (int j = 0; j < len; j++)
                ssrc[b * MM + idx + j] = t * MM + j;
            idx += len;
        }
    }
    __syncthreads();

    for (int i = tid; i < BB * MM; i += THR) g_src[i] = ssrc[i];
}

// ---------------------------------------------------------------------------
// Pass 4: fix-up. src==m (speculation right) -> exit; src<0 -> zero-fill;
// else recompute the correct (t, m_src) projection.
// ---------------------------------------------------------------------------
__global__ __launch_bounds__(THR) void gather_kernel(
    const float* __restrict__ x,
    const float* __restrict__ tmpl,
    const int*   __restrict__ spans,
    float*       __restrict__ out)
{
    const int bm = blockIdx.x;
    const int b = bm >> 6;
    const int m = bm & 63;
    const int tid = threadIdx.x;

    const int src = g_src[b * MM + m];
    if (src == m) return;            // t=0 identity speculation was correct

    float4* orow = (float4*)(out + (size_t)(b * MM + m) * VV);

    if (src < 0) {
        const float4 z = make_float4(0.f, 0.f, 0.f, 0.f);
        for (int c = tid; c < CHUNKS; c += THR) orow[c] = z;
        return;
    }

    const int t  = src >> 6;
    const int ms = src & 63;

    __shared__ float sw[NN];
    __shared__ float swpad;
    if (tid < NN)
        sw[tid] = ((tid + 1) <= spans[b]) ? tmpl[(b * TT + t) * NP1 + tid + 1] : 0.0f;
    if (tid == NN)
        swpad = tmpl[(b * TT + t) * NP1];
    __syncthreads();

    float wl[NN];
#pragma unroll
    for (int n = 0; n < NN; n++) wl[n] = sw[n];

    const float4* xr[NN];
#pragma unroll
    for (int n = 0; n < NN; n++)
        xr[n] = (const float4*)(x + (size_t)((b * NN + n) * MM + ms) * VV);

    for (int c = tid; c < CHUNKS; c += THR) {
        float4 xs[NN];
#pragma unroll
        for (int n = 0; n < NN; n++) xs[n] = xr[n][c];
        float ax = wl[0] * xs[0].x;
        float ay = wl[0] * xs[0].y;
        float az = wl[0] * xs[0].z;
        float aw = wl[0] * xs[0].w;
#pragma unroll
        for (int n = 1; n < NN; n++) {
            ax = fmaf(wl[n], xs[n].x, ax);
            ay = fmaf(wl[n], xs[n].y, ay);
            az = fmaf(wl[n], xs[n].z, az);
            aw = fmaf(wl[n], xs[n].w, aw);
        }
        if (c == 0 && ms == 0) ax += swpad;
        orow[c] = make_float4(ax, ay, az, aw);
    }
}

// ---------------------------------------------------------------------------
extern "C" void kernel_launch(void* const* d_in, const int* in_sizes, int n_in,
                              void* d_out, int out_size)
{
    const float* x     = (const float*)d_in[0];   // [8,6,64,32000] f32
    const float* tmpl  = (const float*)d_in[1];   // [8,8,7] f32
    const int*   spans = (const int*)d_in[2];     // [8] int32
    float*       out   = (float*)d_out;           // [8,64,32000] f32

    t0_kernel<<<BB * MM * 2, THR>>>(x, tmpl, spans, out);
    rest_flags_kernel<<<BB * MM, THR>>>(x, tmpl, spans);
    scan_kernel<<<1, THR>>>();
    gather_kernel<<<BB * MM, THR>>>(x, tmpl, spans, out);
}

// round 16
// speedup vs baseline: 2.2352x; 2.0015x over previous
#include <cuda_runtime.h>

#define BB   8
#define NN   6
#define MM   64
#define VV   32000
#define TT   8
#define NP1  7
#define CHUNKS (VV / 4)     // 8000 float4 per row
#define HC   (CHUNKS / 2)   // 4000 float4 per half-row
#define THR  256
#define NWARP (THR / 32)

// Scratch (__device__ globals; no allocations allowed)
__device__ float         g_pmax[BB * MM * 2];    // per-(b,m,half) max of t=0 projection
__device__ float         g_out0[BB * MM];        // t=0 projection value at v=0 (incl. pad)
__device__ unsigned char g_flags[BB * TT * MM];  // argmax==0 flags for t>=1
__device__ int           g_src[BB * MM];         // t*64 + m_src, or -1

// Weighted accumulate over the NA active (nonzero-weight) rows only.
template<int NA>
__device__ __forceinline__ float4 acc_rows(const float4* const* xr, const float* wl, int c)
{
    float ax = 0.f, ay = 0.f, az = 0.f, aw = 0.f;
    float4 xs[NA > 0 ? NA : 1];
#pragma unroll
    for (int n = 0; n < NA; n++) xs[n] = xr[n][c];
#pragma unroll
    for (int n = 0; n < NA; n++) {
        ax = fmaf(wl[n], xs[n].x, ax);
        ay = fmaf(wl[n], xs[n].y, ay);
        az = fmaf(wl[n], xs[n].z, az);
        aw = fmaf(wl[n], xs[n].w, aw);
    }
    return make_float4(ax, ay, az, aw);
}

// ---------------------------------------------------------------------------
// Pass 1: t=0 projection, split over V-halves (1024 blocks). Reads only the
// spans[b] rows with nonzero weight. Speculative store to d_out + partials.
// ---------------------------------------------------------------------------
template<int NA>
__device__ __forceinline__ void t0_body(
    const float4* const* xr, const float* wl, float4* orow,
    float swpad, int m, int bm, int half, int tid, float* smax)
{
    float vmax = -3.402823466e38f;
    const int cbeg = half * HC, cend = cbeg + HC;
    for (int c = cbeg + tid; c < cend; c += THR) {
        float4 a = acc_rows<NA>(xr, wl, c);
        if (c == 0) {                    // only half 0, tid 0
            if (m == 0) a.x += swpad;    // pad one-hot lands at (m=0, v=0)
            g_out0[bm] = a.x;
        }
        orow[c] = a;                     // speculative t=0 store
        vmax = fmaxf(vmax, fmaxf(fmaxf(a.x, a.y), fmaxf(a.z, a.w)));
    }
#pragma unroll
    for (int o = 16; o > 0; o >>= 1)
        vmax = fmaxf(vmax, __shfl_xor_sync(0xffffffffu, vmax, o));
    if ((tid & 31) == 0) smax[tid >> 5] = vmax;
    __syncthreads();
    if (tid == 0) {
        float v = smax[0];
#pragma unroll
        for (int wd = 1; wd < NWARP; wd++) v = fmaxf(v, smax[wd]);
        g_pmax[bm * 2 + half] = v;
    }
}

__global__ __launch_bounds__(THR) void t0_kernel(
    const float* __restrict__ x,      // [B,N,M,V]
    const float* __restrict__ tmpl,   // [B,T,N+1]
    const int*   __restrict__ spans,  // [B]
    float*       __restrict__ out)    // [B,M,V]
{
    const int bm   = blockIdx.x >> 1;
    const int half = blockIdx.x & 1;
    const int b = bm >> 6;
    const int m = bm & 63;
    const int tid = threadIdx.x;

    __shared__ float sw[NN];
    __shared__ float swpad;
    __shared__ float smax[NWARP];
    __shared__ int   s_nact;

    if (tid < NN)
        sw[tid] = tmpl[(b * TT + 0) * NP1 + tid + 1];   // raw; gating by nact
    if (tid == NN) {
        swpad = tmpl[(b * TT + 0) * NP1];
        int sp = spans[b];
        s_nact = sp < NN ? sp : NN;
    }
    __syncthreads();

    float wl[NN];
#pragma unroll
    for (int n = 0; n < NN; n++) wl[n] = sw[n];
    const int nact = s_nact;

    const float4* xr[NN];
#pragma unroll
    for (int n = 0; n < NN; n++)
        xr[n] = (const float4*)(x + (size_t)((b * NN + n) * MM + m) * VV);
    float4* orow = (float4*)(out + (size_t)(b * MM + m) * VV);

    switch (nact) {
    case 0: t0_body<0>(xr, wl, orow, swpad, m, bm, half, tid, smax); break;
    case 1: t0_body<1>(xr, wl, orow, swpad, m, bm, half, tid, smax); break;
    case 2: t0_body<2>(xr, wl, orow, swpad, m, bm, half, tid, smax); break;
    case 3: t0_body<3>(xr, wl, orow, swpad, m, bm, half, tid, smax); break;
    case 4: t0_body<4>(xr, wl, orow, swpad, m, bm, half, tid, smax); break;
    case 5: t0_body<5>(xr, wl, orow, swpad, m, bm, half, tid, smax); break;
    default: t0_body<6>(xr, wl, orow, swpad, m, bm, half, tid, smax); break;
    }
}

// Helper: t=0 argmax==0 flag for row index i (= b*64+m), from partials.
__device__ __forceinline__ bool t0_flag(int i) {
    return g_out0[i] >= fmaxf(g_pmax[i * 2], g_pmax[i * 2 + 1]);
}

// ---------------------------------------------------------------------------
// Pass 2: flags for t=1..7 — self-gated; reads only active rows.
// ---------------------------------------------------------------------------
template<int NA>
__device__ __forceinline__ void rest_body(
    const float4* const* xr, const float wl[TT][NN], const float* swpad,
    int m, int tid, int b, float smax[NWARP][TT], float* sout0)
{
    float vmax[TT];
#pragma unroll
    for (int t = 1; t < TT; t++) vmax[t] = -3.402823466e38f;

    for (int c = tid; c < CHUNKS; c += THR) {
        float4 xs[NA > 0 ? NA : 1];
#pragma unroll
        for (int n = 0; n < NA; n++) xs[n] = xr[n][c];
#pragma unroll
        for (int t = 1; t < TT; t++) {
            float ax = 0.f, ay = 0.f, az = 0.f, aw = 0.f;
#pragma unroll
            for (int n = 0; n < NA; n++) {
                ax = fmaf(wl[t][n], xs[n].x, ax);
                ay = fmaf(wl[t][n], xs[n].y, ay);
                az = fmaf(wl[t][n], xs[n].z, az);
                aw = fmaf(wl[t][n], xs[n].w, aw);
            }
            if (c == 0) {
                if (m == 0) ax += swpad[t];
                sout0[t] = ax;
            }
            vmax[t] = fmaxf(vmax[t], fmaxf(fmaxf(ax, ay), fmaxf(az, aw)));
        }
    }

#pragma unroll
    for (int t = 1; t < TT; t++) {
        float v = vmax[t];
#pragma unroll
        for (int o = 16; o > 0; o >>= 1)
            v = fmaxf(v, __shfl_xor_sync(0xffffffffu, v, o));
        if ((tid & 31) == 0) smax[tid >> 5][t] = v;
    }
    __syncthreads();
    if (tid >= 1 && tid < TT) {
        float v = smax[0][tid];
#pragma unroll
        for (int wd = 1; wd < NWARP; wd++) v = fmaxf(v, smax[wd][tid]);
        g_flags[(b * TT + tid) * MM + m] = (sout0[tid] >= v) ? 1 : 0;
    }
}

__global__ __launch_bounds__(THR) void rest_flags_kernel(
    const float* __restrict__ x,
    const float* __restrict__ tmpl,
    const int*   __restrict__ spans)
{
    const int bm = blockIdx.x;
    const int b = bm >> 6;
    const int m = bm & 63;
    const int tid = threadIdx.x;
    const int lane = tid & 31;

    __shared__ int s_need;
    if (tid < 32) {
        unsigned lo = __ballot_sync(0xffffffffu, t0_flag(b * MM + lane));
        unsigned hi = __ballot_sync(0xffffffffu, t0_flag(b * MM + 32 + lane));
        if (lane == 0) s_need = (lo | hi) != 0u;
    }
    __syncthreads();
    if (!s_need) return;

    __shared__ float sw[TT][NN];
    __shared__ float swpad[TT];
    __shared__ float smax[NWARP][TT];
    __shared__ float sout0[TT];
    __shared__ int   s_nact;

    if (tid < TT * NN) {
        const int t = tid / NN, n = tid % NN;
        sw[t][n] = tmpl[(b * TT + t) * NP1 + n + 1];
    } else if (tid < TT * NN + TT) {
        const int t = tid - TT * NN;
        swpad[t] = tmpl[(b * TT + t) * NP1];
    } else if (tid == TT * NN + TT) {
        int sp = spans[b];
        s_nact = sp < NN ? sp : NN;
    }
    __syncthreads();

    float wl[TT][NN];
#pragma unroll
    for (int t = 1; t < TT; t++)
#pragma unroll
        for (int n = 0; n < NN; n++) wl[t][n] = sw[t][n];
    const int nact = s_nact;

    const float4* xr[NN];
#pragma unroll
    for (int n = 0; n < NN; n++)
        xr[n] = (const float4*)(x + (size_t)((b * NN + n) * MM + m) * VV);

    switch (nact) {
    case 0: rest_body<0>(xr, wl, swpad, m, tid, b, smax, sout0); break;
    case 1: rest_body<1>(xr, wl, swpad, m, tid, b, smax, sout0); break;
    case 2: rest_body<2>(xr, wl, swpad, m, tid, b, smax, sout0); break;
    case 3: rest_body<3>(xr, wl, swpad, m, tid, b, smax, sout0); break;
    case 4: rest_body<4>(xr, wl, swpad, m, tid, b, smax, sout0); break;
    case 5: rest_body<5>(xr, wl, swpad, m, tid, b, smax, sout0); break;
    default: rest_body<6>(xr, wl, swpad, m, tid, b, smax, sout0); break;
    }
}

// ---------------------------------------------------------------------------
// Pass 3: ballot-based scan (masks via ballots, lengths via ffsll, smem
// cursor, coalesced writeout). Stale t>=1 flags for len0==64 batches are
// never consumed (cursor saturates at 64).
// ---------------------------------------------------------------------------
__global__ __launch_bounds__(THR) void scan_kernel()
{
    __shared__ unsigned long long mask[BB][TT];
    __shared__ int slen[BB][TT];
    __shared__ int ssrc[BB * MM];

    const int tid = threadIdx.x;
    const int warp = tid >> 5, lane = tid & 31;

    for (int i = tid; i < BB * MM; i += THR) ssrc[i] = -1;

    {
        const int b = warp;
        unsigned lo = __ballot_sync(0xffffffffu, t0_flag(b * MM + lane));
        unsigned hi = __ballot_sync(0xffffffffu, t0_flag(b * MM + 32 + lane));
        if (lane == 0)
            mask[b][0] = (unsigned long long)lo | ((unsigned long long)hi << 32);
    }
    for (int rr = warp; rr < BB * (TT - 1); rr += NWARP) {
        const int b = rr / (TT - 1);
        const int t = 1 + rr % (TT - 1);
        const unsigned char* fr = &g_flags[(b * TT + t) * MM];
        unsigned lo = __ballot_sync(0xffffffffu, fr[lane] != 0);
        unsigned hi = __ballot_sync(0xffffffffu, fr[32 + lane] != 0);
        if (lane == 0)
            mask[b][t] = (unsigned long long)lo | ((unsigned long long)hi << 32);
    }
    __syncthreads();

    if (tid < BB * TT) {
        unsigned long long mk = mask[tid >> 3][tid & 7];
        slen[tid >> 3][tid & 7] = mk ? (__ffsll((long long)mk) - 1) : MM;
    }
    __syncthreads();

    if (tid < BB) {
        const int b = tid;
        int idx = 0;
#pragma unroll
        for (int t = 0; t < TT; t++) {
            int len = slen[b][t];
            if (len > MM - idx) len = MM - idx;
            for (int j = 0; j < len; j++)
                ssrc[b * MM + idx + j] = t * MM + j;
            idx += len;
        }
    }
    __syncthreads();

    for (int i = tid; i < BB * MM; i += THR) g_src[i] = ssrc[i];
}

// ---------------------------------------------------------------------------
// Pass 4: fix-up. src==m -> exit; src<0 -> zero-fill; else recompute using
// only the active rows.
// ---------------------------------------------------------------------------
template<int NA>
__device__ __forceinline__ void gather_body(
    const float4* const* xr, const float* wl, float4* orow,
    float swpad, int ms, int tid)
{
    for (int c = tid; c < CHUNKS; c += THR) {
        float4 a = acc_rows<NA>(xr, wl, c);
        if (c == 0 && ms == 0) a.x += swpad;
        orow[c] = a;
    }
}

__global__ __launch_bounds__(THR) void gather_kernel(
    const float* __restrict__ x,
    const float* __restrict__ tmpl,
    const int*   __restrict__ spans,
    float*       __restrict__ out)
{
    const int bm = blockIdx.x;
    const int b = bm >> 6;
    const int m = bm & 63;
    const int tid = threadIdx.x;

    const int src = g_src[b * MM + m];
    if (src == m) return;            // t=0 identity speculation was correct

    float4* orow = (float4*)(out + (size_t)(b * MM + m) * VV);

    if (src < 0) {
        const float4 z = make_float4(0.f, 0.f, 0.f, 0.f);
        for (int c = tid; c < CHUNKS; c += THR) orow[c] = z;
        return;
    }

    const int t  = src >> 6;
    const int ms = src & 63;

    __shared__ float sw[NN];
    __shared__ float swpad;
    __shared__ int   s_nact;
    if (tid < NN)
        sw[tid] = tmpl[(b * TT + t) * NP1 + tid + 1];
    if (tid == NN) {
        swpad = tmpl[(b * TT + t) * NP1];
        int sp = spans[b];
        s_nact = sp < NN ? sp : NN;
    }
    __syncthreads();

    float wl[NN];
#pragma unroll
    for (int n = 0; n < NN; n++) wl[n] = sw[n];
    const int nact = s_nact;

    const float4* xr[NN];
#pragma unroll
    for (int n = 0; n < NN; n++)
        xr[n] = (const float4*)(x + (size_t)((b * NN + n) * MM + ms) * VV);

    switch (nact) {
    case 0: gather_body<0>(xr, wl, orow, swpad, ms, tid); break;
    case 1: gather_body<1>(xr, wl, orow, swpad, ms, tid); break;
    case 2: gather_body<2>(xr, wl, orow, swpad, ms, tid); break;
    case 3: gather_body<3>(xr, wl, orow, swpad, ms, tid); break;
    case 4: gather_body<4>(xr, wl, orow, swpad, ms, tid); break;
    case 5: gather_body<5>(xr, wl, orow, swpad, ms, tid); break;
    default: gather_body<6>(xr, wl, orow, swpad, ms, tid); break;
    }
}

// ---------------------------------------------------------------------------
extern "C" void kernel_launch(void* const* d_in, const int* in_sizes, int n_in,
                              void* d_out, int out_size)
{
    const float* x     = (const float*)d_in[0];   // [8,6,64,32000] f32
    const float* tmpl  = (const float*)d_in[1];   // [8,8,7] f32
    const int*   spans = (const int*)d_in[2];     // [8] int32
    float*       out   = (float*)d_out;           // [8,64,32000] f32

    t0_kernel<<<BB * MM * 2, THR>>>(x, tmpl, spans, out);
    rest_flags_kernel<<<BB * MM, THR>>>(x, tmpl, spans);
    scan_kernel<<<1, THR>>>();
    gather_kernel<<<BB * MM, THR>>>(x, tmpl, spans, out);
}